// round 2
// baseline (speedup 1.0000x reference)
#include <cuda_runtime.h>
#include <cuda_bf16.h>
#include <math.h>
#include <stdint.h>

// ---------------- problem constants ----------------
#define BB 4
#define SS 2048
#define INF_DIM 64
#define DD 128
#define HID 400
#define HH 4
#define KK 20
#define NA 18

#define NTOK 8192          // B*S
#define NTOK2 16384        // 2*B*S (true + sim)
#define NROW 32768         // B*H*S

// output offsets (flattened tuple, C-order concat)
#define OFF_SCORE 0
#define OFF_Y     1
#define OFF_YPRED 32769
#define OFF_YLOW  65537
#define OFF_YHIGH 655361
#define OFF_ERR   1245185
#define OFF_QLOW  1253377
#define OFF_QHIGH 1843201
// total 2433025

__constant__ float c_alphas[NA] = {0.05f,0.06f,0.08f,0.1f,0.12f,0.14f,0.15f,0.17f,0.19f,
                                   0.2f,0.21f,0.23f,0.25f,0.3f,0.35f,0.38f,0.4f,0.45f};

// ---------------- scratch (static device allocations) ----------------
__device__ float g_h1[NTOK2 * HID];
__device__ float g_h2[NTOK2 * HID];
__device__ float g_enc[NTOK2 * DD];
__device__ float g_ln[NTOK2 * DD];
__device__ float g_qk[NTOK2 * (HH * DD)];
__device__ float g_scores[(size_t)BB * HH * SS * SS];   // 256 MB
__device__ float g_rowsq[NROW];

// ---------------- generic SGEMM: C = act(A @ W + bias) ----------------
// A row-major MxK (lda), W row-major KxN (ldw), C row-major (ldc).
// M % 128 == 0, K % 8 == 0 guaranteed by caller. N may be ragged.
__global__ __launch_bounds__(256) void sgemm_bias(
    const float* __restrict__ A, int lda,
    const float* __restrict__ W, int ldw,
    const float* __restrict__ bias,
    float* __restrict__ C, int ldc,
    int N, int K, int relu)
{
    __shared__ float As[8][128];
    __shared__ float Ws[8][128];
    const int tid = threadIdx.x;
    const int row0 = blockIdx.y * 128;
    const int col0 = blockIdx.x * 128;
    const int m0 = (tid >> 4) << 3;
    const int n0 = (tid & 15) << 3;
    const int ar = tid >> 1;          // 0..127
    const int ac = (tid & 1) << 2;    // 0 or 4
    const int wr = tid >> 5;          // 0..7
    const int wc = (tid & 31) << 2;   // 0..124

    float acc[8][8];
#pragma unroll
    for (int i = 0; i < 8; i++)
#pragma unroll
        for (int j = 0; j < 8; j++) acc[i][j] = 0.f;

    const bool fullN = (col0 + 128 <= N);

    for (int k0 = 0; k0 < K; k0 += 8) {
        float4 av = *reinterpret_cast<const float4*>(A + (size_t)(row0 + ar) * lda + k0 + ac);
        float4 wv;
        if (fullN) {
            wv = *reinterpret_cast<const float4*>(W + (size_t)(k0 + wr) * ldw + col0 + wc);
        } else {
            const float* wp = W + (size_t)(k0 + wr) * ldw;
            wv.x = (col0 + wc + 0 < N) ? wp[col0 + wc + 0] : 0.f;
            wv.y = (col0 + wc + 1 < N) ? wp[col0 + wc + 1] : 0.f;
            wv.z = (col0 + wc + 2 < N) ? wp[col0 + wc + 2] : 0.f;
            wv.w = (col0 + wc + 3 < N) ? wp[col0 + wc + 3] : 0.f;
        }
        As[ac + 0][ar] = av.x;
        As[ac + 1][ar] = av.y;
        As[ac + 2][ar] = av.z;
        As[ac + 3][ar] = av.w;
        *reinterpret_cast<float4*>(&Ws[wr][wc]) = wv;
        __syncthreads();
#pragma unroll
        for (int kk = 0; kk < 8; kk++) {
            float a[8], w[8];
#pragma unroll
            for (int i = 0; i < 8; i++) a[i] = As[kk][m0 + i];
#pragma unroll
            for (int j = 0; j < 8; j++) w[j] = Ws[kk][n0 + j];
#pragma unroll
            for (int i = 0; i < 8; i++)
#pragma unroll
                for (int j = 0; j < 8; j++) acc[i][j] = fmaf(a[i], w[j], acc[i][j]);
        }
        __syncthreads();
    }

#pragma unroll
    for (int j = 0; j < 8; j++) {
        int c = col0 + n0 + j;
        if (c < N) {
            float bb = bias[c];
#pragma unroll
            for (int i = 0; i < 8; i++) {
                float v = acc[i][j] + bb;
                if (relu) v = fmaxf(v, 0.f);
                C[(size_t)(row0 + m0 + i) * ldc + c] = v;
            }
        }
    }
}

// ---------------- scores GEMM (NT): S[s][m] = (q_s . k_m)/sqrt(D), diag=-inf ----
__global__ __launch_bounds__(256) void sgemm_nt_scores(
    const float* __restrict__ Qb, const float* __restrict__ Kb)
{
    const int bh = blockIdx.z;
    const int b = bh >> 2, h = bh & 3;
    const float* A = Qb + (size_t)b * SS * (HH * DD) + h * DD;
    const float* Bm = Kb + (size_t)b * SS * (HH * DD) + h * DD;
    float* C = g_scores + (size_t)bh * SS * SS;

    __shared__ float As[8][128];
    __shared__ float Bs[8][128];
    const int tid = threadIdx.x;
    const int row0 = blockIdx.y * 128;
    const int col0 = blockIdx.x * 128;
    const int m0 = (tid >> 4) << 3;
    const int n0 = (tid & 15) << 3;
    const int ar = tid >> 1;
    const int ac = (tid & 1) << 2;

    float acc[8][8];
#pragma unroll
    for (int i = 0; i < 8; i++)
#pragma unroll
        for (int j = 0; j < 8; j++) acc[i][j] = 0.f;

    for (int k0 = 0; k0 < DD; k0 += 8) {
        float4 av = *reinterpret_cast<const float4*>(A + (size_t)(row0 + ar) * (HH * DD) + k0 + ac);
        float4 bv = *reinterpret_cast<const float4*>(Bm + (size_t)(col0 + ar) * (HH * DD) + k0 + ac);
        As[ac + 0][ar] = av.x; As[ac + 1][ar] = av.y; As[ac + 2][ar] = av.z; As[ac + 3][ar] = av.w;
        Bs[ac + 0][ar] = bv.x; Bs[ac + 1][ar] = bv.y; Bs[ac + 2][ar] = bv.z; Bs[ac + 3][ar] = bv.w;
        __syncthreads();
#pragma unroll
        for (int kk = 0; kk < 8; kk++) {
            float a[8], w[8];
#pragma unroll
            for (int i = 0; i < 8; i++) a[i] = As[kk][m0 + i];
#pragma unroll
            for (int j = 0; j < 8; j++) w[j] = Bs[kk][n0 + j];
#pragma unroll
            for (int i = 0; i < 8; i++)
#pragma unroll
                for (int j = 0; j < 8; j++) acc[i][j] = fmaf(a[i], w[j], acc[i][j]);
        }
        __syncthreads();
    }

    const float scale = 0.08838834764831845f; // 1/sqrt(128)
    const float ninf = __int_as_float(0xff800000);
#pragma unroll
    for (int i = 0; i < 8; i++) {
        int r = row0 + m0 + i;
#pragma unroll
        for (int j = 0; j < 8; j++) {
            int c = col0 + n0 + j;
            float v = acc[i][j] * scale;
            if (r == c) v = ninf;
            C[(size_t)r * SS + c] = v;
        }
    }
}

// ---------------- LayerNorm (warp per row) ----------------
__global__ __launch_bounds__(256) void ln_kernel(
    const float* __restrict__ gq, const float* __restrict__ bq,
    const float* __restrict__ gk, const float* __restrict__ bk)
{
    const int warp = threadIdx.x >> 5, lane = threadIdx.x & 31;
    const int row = blockIdx.x * 8 + warp;
    const float* x = g_enc + (size_t)row * DD;
    float v0 = x[lane], v1 = x[lane + 32], v2 = x[lane + 64], v3 = x[lane + 96];
    float s = v0 + v1 + v2 + v3;
#pragma unroll
    for (int o = 16; o; o >>= 1) s += __shfl_xor_sync(0xffffffffu, s, o);
    float mu = s * (1.f / 128.f);
    float d0 = v0 - mu, d1 = v1 - mu, d2 = v2 - mu, d3 = v3 - mu;
    float sq = d0 * d0 + d1 * d1 + d2 * d2 + d3 * d3;
#pragma unroll
    for (int o = 16; o; o >>= 1) sq += __shfl_xor_sync(0xffffffffu, sq, o);
    float rs = rsqrtf(sq * (1.f / 128.f) + 1e-5f);
    const float* g = (row < NTOK) ? gq : gk;
    const float* be = (row < NTOK) ? bq : bk;
    float* o = g_ln + (size_t)row * DD;
    o[lane]      = d0 * rs * g[lane]      + be[lane];
    o[lane + 32] = d1 * rs * g[lane + 32] + be[lane + 32];
    o[lane + 64] = d2 * rs * g[lane + 64] + be[lane + 64];
    o[lane + 96] = d3 * rs * g[lane + 96] + be[lane + 96];
}

// ---------------- top-K + quantiles (warp per row) ----------------
__global__ __launch_bounds__(128) void topk_quantile_kernel(
    const float* __restrict__ errors,
    const float* __restrict__ y,
    const float* __restrict__ y_pred,
    float* __restrict__ out)
{
    __shared__ float s_v[4][KK * 32];
    __shared__ int   s_i[4][KK * 32];
    __shared__ float s_sorted[4][KK];

    const int warp = threadIdx.x >> 5, lane = threadIdx.x & 31;
    const int row = blockIdx.x * 4 + warp;           // < 32768
    const int b = row >> 13;
    const int h = (row >> 11) & 3;
    const int s = row & 2047;
    const float* sr = g_scores + (size_t)row * SS;
    const float ninf = __int_as_float(0xff800000);

#pragma unroll
    for (int t = 0; t < KK; t++) s_v[warp][t * 32 + lane] = ninf;

    // per-lane streaming insertion top-20 (coalesced over m)
    for (int j = 0; j < SS / 32; j++) {
        int m = j * 32 + lane;
        float x = sr[m];
        if (x > s_v[warp][(KK - 1) * 32 + lane]) {
            int t = KK - 1;
            while (t > 0 && s_v[warp][(t - 1) * 32 + lane] < x) {
                s_v[warp][t * 32 + lane] = s_v[warp][(t - 1) * 32 + lane];
                s_i[warp][t * 32 + lane] = s_i[warp][(t - 1) * 32 + lane];
                t--;
            }
            s_v[warp][t * 32 + lane] = x;
            s_i[warp][t * 32 + lane] = m;
        }
    }
    __syncwarp();

    // 20-round merge via warp argmax
    int p = 0;
    int my_m = 0;
    for (int r = 0; r < KK; r++) {
        float cand = (p < KK) ? s_v[warp][p * 32 + lane] : ninf;
        float bv = cand; int bl = lane;
#pragma unroll
        for (int off = 16; off; off >>= 1) {
            float ov = __shfl_down_sync(0xffffffffu, bv, off);
            int   ol = __shfl_down_sync(0xffffffffu, bl, off);
            if (ov > bv) { bv = ov; bl = ol; }
        }
        bl = __shfl_sync(0xffffffffu, bl, 0);
        int mi = (lane == bl && p < KK) ? s_i[warp][p * 32 + lane] : 0;
        mi = __shfl_sync(0xffffffffu, mi, bl);
        if (lane == bl) p++;
        if (lane == r) my_m = mi;
    }

    // gather err values for the selected m's
    float e = 0.f;
    if (lane < KK) e = errors[((size_t)(b * SS + my_m)) * 4 + 0];

    // rank-sort 20 values across lanes
    int rank = 0;
#pragma unroll
    for (int j = 0; j < KK; j++) {
        float ej = __shfl_sync(0xffffffffu, e, j);
        if (lane < KK && ((ej < e) || (ej == e && j < lane))) rank++;
    }
    if (lane < KK) s_sorted[warp][rank] = e;
    __syncwarp();

    const float yp = y_pred[((size_t)(b * SS + s)) * 4 + 0];
    float ql = 0.f, qh = 0.f;
    if (lane < NA) {
        float alpha = c_alphas[lane];
        float pl = 0.5f * alpha * (float)(KK - 1);
        int il = (int)pl; float fl = pl - (float)il;
        ql = s_sorted[warp][il] + fl * (s_sorted[warp][il + 1] - s_sorted[warp][il]);
        float ph = (1.f - 0.5f * alpha) * (float)(KK - 1);
        int ih = (int)ph; float fh = ph - (float)ih;
        qh = s_sorted[warp][ih] + fh * (s_sorted[warp][ih + 1] - s_sorted[warp][ih]);
        size_t oidx = ((size_t)((h * BB + b) * NA + lane)) * SS + s;
        out[OFF_QLOW  + oidx] = ql;
        out[OFF_QHIGH + oidx] = qh;
        out[OFF_YLOW  + oidx] = ql + yp;
        out[OFF_YHIGH + oidx] = qh + yp;
    }

    // mean of 36 quantiles -> per-row squared error
    float t = ql + qh;
#pragma unroll
    for (int o = 16; o; o >>= 1) t += __shfl_down_sync(0xffffffffu, t, o);
    if (lane == 0) {
        float me = t * (1.f / 36.f);
        float yt = y[((size_t)(b * SS + s)) * 4 + 0];
        float d = yt - (me + yp);
        g_rowsq[row] = d * d;
    }
}

// ---------------- passthrough copies ----------------
__global__ void copy_kernel(const float* __restrict__ y,
                            const float* __restrict__ yp,
                            const float* __restrict__ err,
                            float* __restrict__ out)
{
    int i = blockIdx.x * blockDim.x + threadIdx.x;
    if (i < 32768) out[OFF_Y + i] = y[i];
    else if (i < 65536) out[OFF_YPRED + (i - 32768)] = yp[i - 32768];
    else if (i < 73728) { int j = i - 65536; out[OFF_ERR + j] = err[(size_t)j * 4]; }
}

// ---------------- final scalar reduce ----------------
__global__ void reduce_kernel(float* __restrict__ out)
{
    __shared__ float sh[1024];
    float s = 0.f;
    for (int i = threadIdx.x; i < NROW; i += 1024) s += g_rowsq[i];
    sh[threadIdx.x] = s;
    __syncthreads();
    for (int o = 512; o; o >>= 1) {
        if (threadIdx.x < o) sh[threadIdx.x] += sh[threadIdx.x + o];
        __syncthreads();
    }
    if (threadIdx.x == 0) out[OFF_SCORE] = sh[0] * (1.f / (float)NROW);
}

// ---------------- launch ----------------
extern "C" void kernel_launch(void* const* d_in, const int* in_sizes, int n_in,
                              void* d_out, int out_size)
{
    const float* Xt   = (const float*)d_in[0];
    const float* Xs   = (const float*)d_in[1];
    const float* err  = (const float*)d_in[2];
    const float* y    = (const float*)d_in[3];
    const float* ypr  = (const float*)d_in[4];
    const float* W1   = (const float*)d_in[5];
    const float* b1   = (const float*)d_in[6];
    const float* W2   = (const float*)d_in[7];
    const float* b2   = (const float*)d_in[8];
    const float* W3   = (const float*)d_in[9];
    const float* b3   = (const float*)d_in[10];
    const float* W4   = (const float*)d_in[11];
    const float* b4   = (const float*)d_in[12];
    const float* Wq   = (const float*)d_in[13];
    const float* bq   = (const float*)d_in[14];
    const float* Wk   = (const float*)d_in[15];
    const float* bk   = (const float*)d_in[16];
    const float* gq   = (const float*)d_in[17];
    const float* betaq= (const float*)d_in[18];
    const float* gk   = (const float*)d_in[19];
    const float* betak= (const float*)d_in[20];
    float* out = (float*)d_out;

    float *p_h1, *p_h2, *p_enc, *p_ln, *p_qk;
    cudaGetSymbolAddress((void**)&p_h1, g_h1);
    cudaGetSymbolAddress((void**)&p_h2, g_h2);
    cudaGetSymbolAddress((void**)&p_enc, g_enc);
    cudaGetSymbolAddress((void**)&p_ln, g_ln);
    cudaGetSymbolAddress((void**)&p_qk, g_qk);

    // MLP layer 1 (two halves: true rows [0,8192), sim rows [8192,16384))
    sgemm_bias<<<dim3(4, 64), 256>>>(Xt, INF_DIM, W1, HID, b1, p_h1, HID, HID, INF_DIM, 1);
    sgemm_bias<<<dim3(4, 64), 256>>>(Xs, INF_DIM, W1, HID, b1, p_h1 + (size_t)NTOK * HID, HID, HID, INF_DIM, 1);
    // layers 2,3
    sgemm_bias<<<dim3(4, 128), 256>>>(p_h1, HID, W2, HID, b2, p_h2, HID, HID, HID, 1);
    sgemm_bias<<<dim3(4, 128), 256>>>(p_h2, HID, W3, HID, b3, p_h1, HID, HID, HID, 1);
    // layer 4 (no relu) -> enc
    sgemm_bias<<<dim3(1, 128), 256>>>(p_h1, HID, W4, DD, b4, p_enc, DD, DD, HID, 0);
    // layernorm
    ln_kernel<<<NTOK2 / 8, 256>>>(gq, betaq, gk, betak);
    // projections: q (rows 0..8191), k (rows 8192..16383)
    sgemm_bias<<<dim3(4, 64), 256>>>(p_ln, DD, Wq, HH * DD, bq, p_qk, HH * DD, HH * DD, DD, 0);
    sgemm_bias<<<dim3(4, 64), 256>>>(p_ln + (size_t)NTOK * DD, DD, Wk, HH * DD, bk,
                                     p_qk + (size_t)NTOK * (HH * DD), HH * DD, HH * DD, DD, 0);
    // scores (16 independent 2048x2048x128 NT gemms)
    sgemm_nt_scores<<<dim3(16, 16, 16), 256>>>(p_qk, p_qk + (size_t)NTOK * (HH * DD));
    // top-k + quantiles + quantile outputs
    topk_quantile_kernel<<<NROW / 4, 128>>>(err, y, ypr, out);
    // passthrough copies
    copy_kernel<<<288, 256>>>(y, ypr, err, out);
    // scalar score
    reduce_kernel<<<1, 1024>>>(out);
}

// round 3
// speedup vs baseline: 1.1194x; 1.1194x over previous
#include <cuda_runtime.h>
#include <cuda_bf16.h>
#include <math.h>
#include <stdint.h>

// ---------------- problem constants ----------------
#define BB 4
#define SS 2048
#define INF_DIM 64
#define DD 128
#define HID 400
#define HH 4
#define KK 20
#define NA 18

#define NTOK 8192          // B*S
#define NTOK2 16384        // 2*B*S (true + sim)
#define NROW 32768         // B*H*S

// output offsets (flattened tuple, C-order concat)
#define OFF_SCORE 0
#define OFF_Y     1
#define OFF_YPRED 32769
#define OFF_YLOW  65537
#define OFF_YHIGH 655361
#define OFF_ERR   1245185
#define OFF_QLOW  1253377
#define OFF_QHIGH 1843201
// total 2433025

__constant__ float c_alphas[NA] = {0.05f,0.06f,0.08f,0.1f,0.12f,0.14f,0.15f,0.17f,0.19f,
                                   0.2f,0.21f,0.23f,0.25f,0.3f,0.35f,0.38f,0.4f,0.45f};

// ---------------- scratch (static device allocations) ----------------
__device__ float g_h1[NTOK2 * HID];
__device__ float g_h2[NTOK2 * HID];
__device__ float g_enc[NTOK2 * DD];
__device__ float g_ln[NTOK2 * DD];
__device__ float g_qk[NTOK2 * (HH * DD)];
__device__ float g_scores[(size_t)BB * HH * SS * SS];   // 256 MB
__device__ float g_rowsq[NROW];

// ---------------- generic SGEMM: C = act(A @ W + bias) ----------------
// A row-major MxK (lda), W row-major KxN (ldw), C row-major (ldc).
// M % 128 == 0, K % 8 == 0. N may be ragged.
// 128x128 tile, 8x8 microtile, double-buffered smem, LDS.128 fragments.
__global__ __launch_bounds__(256) void sgemm_bias(
    const float* __restrict__ A, int lda,
    const float* __restrict__ W, int ldw,
    const float* __restrict__ bias,
    float* __restrict__ C, int ldc,
    int N, int K, int relu)
{
    __shared__ float As[2][8][128];
    __shared__ float Ws[2][8][128];
    const int tid = threadIdx.x;
    const int row0 = blockIdx.y * 128;
    const int col0 = blockIdx.x * 128;
    const int m0 = (tid >> 4) << 3;
    const int n0 = (tid & 15) << 3;
    const int ar = tid >> 1;          // 0..127
    const int ac = (tid & 1) << 2;    // 0 or 4
    const int wr = tid >> 5;          // 0..7
    const int wc = (tid & 31) << 2;   // 0..124
    const bool fullN = (col0 + 128 <= N);

    const float* Ap = A + (size_t)(row0 + ar) * lda + ac;

    float acc[8][8];
#pragma unroll
    for (int i = 0; i < 8; i++)
#pragma unroll
        for (int j = 0; j < 8; j++) acc[i][j] = 0.f;

    const int nk = K >> 3;

    // prologue: tile 0 -> buf 0
    float4 av = *reinterpret_cast<const float4*>(Ap);
    float4 wv;
    {
        const float* wp = W + (size_t)wr * ldw + col0 + wc;
        if (fullN) wv = *reinterpret_cast<const float4*>(wp);
        else {
            wv.x = (col0 + wc + 0 < N) ? wp[0] : 0.f;
            wv.y = (col0 + wc + 1 < N) ? wp[1] : 0.f;
            wv.z = (col0 + wc + 2 < N) ? wp[2] : 0.f;
            wv.w = (col0 + wc + 3 < N) ? wp[3] : 0.f;
        }
    }
    As[0][ac + 0][ar] = av.x; As[0][ac + 1][ar] = av.y;
    As[0][ac + 2][ar] = av.z; As[0][ac + 3][ar] = av.w;
    *reinterpret_cast<float4*>(&Ws[0][wr][wc]) = wv;
    __syncthreads();

    int buf = 0;
    for (int t = 0; t < nk; t++) {
        const bool more = (t + 1 < nk);
        if (more) {
            const int k0 = (t + 1) << 3;
            av = *reinterpret_cast<const float4*>(Ap + k0);
            const float* wp = W + (size_t)(k0 + wr) * ldw + col0 + wc;
            if (fullN) wv = *reinterpret_cast<const float4*>(wp);
            else {
                wv.x = (col0 + wc + 0 < N) ? wp[0] : 0.f;
                wv.y = (col0 + wc + 1 < N) ? wp[1] : 0.f;
                wv.z = (col0 + wc + 2 < N) ? wp[2] : 0.f;
                wv.w = (col0 + wc + 3 < N) ? wp[3] : 0.f;
            }
        }
#pragma unroll
        for (int kk = 0; kk < 8; kk++) {
            float4 a0 = *reinterpret_cast<const float4*>(&As[buf][kk][m0]);
            float4 a1 = *reinterpret_cast<const float4*>(&As[buf][kk][m0 + 4]);
            float4 w0 = *reinterpret_cast<const float4*>(&Ws[buf][kk][n0]);
            float4 w1 = *reinterpret_cast<const float4*>(&Ws[buf][kk][n0 + 4]);
            float a[8] = {a0.x, a0.y, a0.z, a0.w, a1.x, a1.y, a1.z, a1.w};
            float w[8] = {w0.x, w0.y, w0.z, w0.w, w1.x, w1.y, w1.z, w1.w};
#pragma unroll
            for (int i = 0; i < 8; i++)
#pragma unroll
                for (int j = 0; j < 8; j++) acc[i][j] = fmaf(a[i], w[j], acc[i][j]);
        }
        if (more) {
            const int nb = buf ^ 1;
            As[nb][ac + 0][ar] = av.x; As[nb][ac + 1][ar] = av.y;
            As[nb][ac + 2][ar] = av.z; As[nb][ac + 3][ar] = av.w;
            *reinterpret_cast<float4*>(&Ws[nb][wr][wc]) = wv;
            __syncthreads();
            buf = nb;
        }
    }

#pragma unroll
    for (int j = 0; j < 8; j++) {
        int c = col0 + n0 + j;
        if (c < N) {
            float bb = bias[c];
#pragma unroll
            for (int i = 0; i < 8; i++) {
                float v = acc[i][j] + bb;
                if (relu) v = fmaxf(v, 0.f);
                C[(size_t)(row0 + m0 + i) * ldc + c] = v;
            }
        }
    }
}

// ---------------- scores GEMM (NT): S[s][m] = (q_s . k_m)/sqrt(D), diag=-inf ----
__global__ __launch_bounds__(256) void sgemm_nt_scores(
    const float* __restrict__ Qb, const float* __restrict__ Kb)
{
    const int bh = blockIdx.z;
    const int b = bh >> 2, h = bh & 3;
    const float* A  = Qb + (size_t)b * SS * (HH * DD) + h * DD;
    const float* Bm = Kb + (size_t)b * SS * (HH * DD) + h * DD;
    float* C = g_scores + (size_t)bh * SS * SS;

    __shared__ float As[2][8][128];
    __shared__ float Bs[2][8][128];
    const int tid = threadIdx.x;
    const int row0 = blockIdx.y * 128;
    const int col0 = blockIdx.x * 128;
    const int m0 = (tid >> 4) << 3;
    const int n0 = (tid & 15) << 3;
    const int ar = tid >> 1;
    const int ac = (tid & 1) << 2;

    const float* Ap = A  + (size_t)(row0 + ar) * (HH * DD) + ac;
    const float* Bp = Bm + (size_t)(col0 + ar) * (HH * DD) + ac;

    float acc[8][8];
#pragma unroll
    for (int i = 0; i < 8; i++)
#pragma unroll
        for (int j = 0; j < 8; j++) acc[i][j] = 0.f;

    // prologue
    float4 av = *reinterpret_cast<const float4*>(Ap);
    float4 bv = *reinterpret_cast<const float4*>(Bp);
    As[0][ac + 0][ar] = av.x; As[0][ac + 1][ar] = av.y;
    As[0][ac + 2][ar] = av.z; As[0][ac + 3][ar] = av.w;
    Bs[0][ac + 0][ar] = bv.x; Bs[0][ac + 1][ar] = bv.y;
    Bs[0][ac + 2][ar] = bv.z; Bs[0][ac + 3][ar] = bv.w;
    __syncthreads();

    int buf = 0;
#pragma unroll 1
    for (int t = 0; t < DD / 8; t++) {
        const bool more = (t + 1 < DD / 8);
        if (more) {
            const int k0 = (t + 1) << 3;
            av = *reinterpret_cast<const float4*>(Ap + k0);
            bv = *reinterpret_cast<const float4*>(Bp + k0);
        }
#pragma unroll
        for (int kk = 0; kk < 8; kk++) {
            float4 a0 = *reinterpret_cast<const float4*>(&As[buf][kk][m0]);
            float4 a1 = *reinterpret_cast<const float4*>(&As[buf][kk][m0 + 4]);
            float4 w0 = *reinterpret_cast<const float4*>(&Bs[buf][kk][n0]);
            float4 w1 = *reinterpret_cast<const float4*>(&Bs[buf][kk][n0 + 4]);
            float a[8] = {a0.x, a0.y, a0.z, a0.w, a1.x, a1.y, a1.z, a1.w};
            float w[8] = {w0.x, w0.y, w0.z, w0.w, w1.x, w1.y, w1.z, w1.w};
#pragma unroll
            for (int i = 0; i < 8; i++)
#pragma unroll
                for (int j = 0; j < 8; j++) acc[i][j] = fmaf(a[i], w[j], acc[i][j]);
        }
        if (more) {
            const int nb = buf ^ 1;
            As[nb][ac + 0][ar] = av.x; As[nb][ac + 1][ar] = av.y;
            As[nb][ac + 2][ar] = av.z; As[nb][ac + 3][ar] = av.w;
            Bs[nb][ac + 0][ar] = bv.x; Bs[nb][ac + 1][ar] = bv.y;
            Bs[nb][ac + 2][ar] = bv.z; Bs[nb][ac + 3][ar] = bv.w;
            __syncthreads();
            buf = nb;
        }
    }

    const float scale = 0.08838834764831845f; // 1/sqrt(128)
    const float ninf = __int_as_float(0xff800000);
#pragma unroll
    for (int i = 0; i < 8; i++) {
        int r = row0 + m0 + i;
        float4 v0, v1;
        float* vv = &v0.x;
        // compute 8 scaled values
        float tmp[8];
#pragma unroll
        for (int j = 0; j < 8; j++) {
            int c = col0 + n0 + j;
            float v = acc[i][j] * scale;
            tmp[j] = (r == c) ? ninf : v;
        }
        v0.x = tmp[0]; v0.y = tmp[1]; v0.z = tmp[2]; v0.w = tmp[3];
        v1.x = tmp[4]; v1.y = tmp[5]; v1.z = tmp[6]; v1.w = tmp[7];
        (void)vv;
        float* cp = C + (size_t)r * SS + col0 + n0;
        *reinterpret_cast<float4*>(cp)     = v0;
        *reinterpret_cast<float4*>(cp + 4) = v1;
    }
}

// ---------------- LayerNorm (warp per row) ----------------
__global__ __launch_bounds__(256) void ln_kernel(
    const float* __restrict__ gq, const float* __restrict__ bq,
    const float* __restrict__ gk, const float* __restrict__ bk)
{
    const int warp = threadIdx.x >> 5, lane = threadIdx.x & 31;
    const int row = blockIdx.x * 8 + warp;
    const float* x = g_enc + (size_t)row * DD;
    float v0 = x[lane], v1 = x[lane + 32], v2 = x[lane + 64], v3 = x[lane + 96];
    float s = v0 + v1 + v2 + v3;
#pragma unroll
    for (int o = 16; o; o >>= 1) s += __shfl_xor_sync(0xffffffffu, s, o);
    float mu = s * (1.f / 128.f);
    float d0 = v0 - mu, d1 = v1 - mu, d2 = v2 - mu, d3 = v3 - mu;
    float sq = d0 * d0 + d1 * d1 + d2 * d2 + d3 * d3;
#pragma unroll
    for (int o = 16; o; o >>= 1) sq += __shfl_xor_sync(0xffffffffu, sq, o);
    float rs = rsqrtf(sq * (1.f / 128.f) + 1e-5f);
    const float* g = (row < NTOK) ? gq : gk;
    const float* be = (row < NTOK) ? bq : bk;
    float* o = g_ln + (size_t)row * DD;
    o[lane]      = d0 * rs * g[lane]      + be[lane];
    o[lane + 32] = d1 * rs * g[lane + 32] + be[lane + 32];
    o[lane + 64] = d2 * rs * g[lane + 64] + be[lane + 64];
    o[lane + 96] = d3 * rs * g[lane + 96] + be[lane + 96];
}

// ---------------- top-K + quantiles (warp per row) ----------------
__global__ __launch_bounds__(128) void topk_quantile_kernel(
    const float* __restrict__ errors,
    const float* __restrict__ y,
    const float* __restrict__ y_pred,
    float* __restrict__ out)
{
    __shared__ float s_v[4][KK * 32];
    __shared__ int   s_i[4][KK * 32];
    __shared__ float s_sorted[4][KK];

    const int warp = threadIdx.x >> 5, lane = threadIdx.x & 31;
    const int row = blockIdx.x * 4 + warp;           // < 32768
    const int b = row >> 13;
    const int h = (row >> 11) & 3;
    const int s = row & 2047;
    const float* sr = g_scores + (size_t)row * SS;
    const float ninf = __int_as_float(0xff800000);

#pragma unroll
    for (int t = 0; t < KK; t++) s_v[warp][t * 32 + lane] = ninf;

    // per-lane streaming insertion top-20 (coalesced over m)
    for (int j = 0; j < SS / 32; j++) {
        int m = j * 32 + lane;
        float x = sr[m];
        if (x > s_v[warp][(KK - 1) * 32 + lane]) {
            int t = KK - 1;
            while (t > 0 && s_v[warp][(t - 1) * 32 + lane] < x) {
                s_v[warp][t * 32 + lane] = s_v[warp][(t - 1) * 32 + lane];
                s_i[warp][t * 32 + lane] = s_i[warp][(t - 1) * 32 + lane];
                t--;
            }
            s_v[warp][t * 32 + lane] = x;
            s_i[warp][t * 32 + lane] = m;
        }
    }
    __syncwarp();

    // 20-round merge via warp argmax
    int p = 0;
    int my_m = 0;
    for (int r = 0; r < KK; r++) {
        float cand = (p < KK) ? s_v[warp][p * 32 + lane] : ninf;
        float bv = cand; int bl = lane;
#pragma unroll
        for (int off = 16; off; off >>= 1) {
            float ov = __shfl_down_sync(0xffffffffu, bv, off);
            int   ol = __shfl_down_sync(0xffffffffu, bl, off);
            if (ov > bv) { bv = ov; bl = ol; }
        }
        bl = __shfl_sync(0xffffffffu, bl, 0);
        int mi = (lane == bl && p < KK) ? s_i[warp][p * 32 + lane] : 0;
        mi = __shfl_sync(0xffffffffu, mi, bl);
        if (lane == bl) p++;
        if (lane == r) my_m = mi;
    }

    // gather err values for the selected m's
    float e = 0.f;
    if (lane < KK) e = errors[((size_t)(b * SS + my_m)) * 4 + 0];

    // rank-sort 20 values across lanes
    int rank = 0;
#pragma unroll
    for (int j = 0; j < KK; j++) {
        float ej = __shfl_sync(0xffffffffu, e, j);
        if (lane < KK && ((ej < e) || (ej == e && j < lane))) rank++;
    }
    if (lane < KK) s_sorted[warp][rank] = e;
    __syncwarp();

    const float yp = y_pred[((size_t)(b * SS + s)) * 4 + 0];
    float ql = 0.f, qh = 0.f;
    if (lane < NA) {
        float alpha = c_alphas[lane];
        float pl = 0.5f * alpha * (float)(KK - 1);
        int il = (int)pl; float fl = pl - (float)il;
        ql = s_sorted[warp][il] + fl * (s_sorted[warp][il + 1] - s_sorted[warp][il]);
        float ph = (1.f - 0.5f * alpha) * (float)(KK - 1);
        int ih = (int)ph; float fh = ph - (float)ih;
        qh = s_sorted[warp][ih] + fh * (s_sorted[warp][ih + 1] - s_sorted[warp][ih]);
        size_t oidx = ((size_t)((h * BB + b) * NA + lane)) * SS + s;
        out[OFF_QLOW  + oidx] = ql;
        out[OFF_QHIGH + oidx] = qh;
        out[OFF_YLOW  + oidx] = ql + yp;
        out[OFF_YHIGH + oidx] = qh + yp;
    }

    // mean of 36 quantiles -> per-row squared error
    float t = ql + qh;
#pragma unroll
    for (int o = 16; o; o >>= 1) t += __shfl_down_sync(0xffffffffu, t, o);
    if (lane == 0) {
        float me = t * (1.f / 36.f);
        float yt = y[((size_t)(b * SS + s)) * 4 + 0];
        float d = yt - (me + yp);
        g_rowsq[row] = d * d;
    }
}

// ---------------- passthrough copies ----------------
__global__ void copy_kernel(const float* __restrict__ y,
                            const float* __restrict__ yp,
                            const float* __restrict__ err,
                            float* __restrict__ out)
{
    int i = blockIdx.x * blockDim.x + threadIdx.x;
    if (i < 32768) out[OFF_Y + i] = y[i];
    else if (i < 65536) out[OFF_YPRED + (i - 32768)] = yp[i - 32768];
    else if (i < 73728) { int j = i - 65536; out[OFF_ERR + j] = err[(size_t)j * 4]; }
}

// ---------------- final scalar reduce ----------------
__global__ void reduce_kernel(float* __restrict__ out)
{
    __shared__ float sh[1024];
    float s = 0.f;
    for (int i = threadIdx.x; i < NROW; i += 1024) s += g_rowsq[i];
    sh[threadIdx.x] = s;
    __syncthreads();
    for (int o = 512; o; o >>= 1) {
        if (threadIdx.x < o) sh[threadIdx.x] += sh[threadIdx.x + o];
        __syncthreads();
    }
    if (threadIdx.x == 0) out[OFF_SCORE] = sh[0] * (1.f / (float)NROW);
}

// ---------------- launch ----------------
extern "C" void kernel_launch(void* const* d_in, const int* in_sizes, int n_in,
                              void* d_out, int out_size)
{
    const float* Xt   = (const float*)d_in[0];
    const float* Xs   = (const float*)d_in[1];
    const float* err  = (const float*)d_in[2];
    const float* y    = (const float*)d_in[3];
    const float* ypr  = (const float*)d_in[4];
    const float* W1   = (const float*)d_in[5];
    const float* b1   = (const float*)d_in[6];
    const float* W2   = (const float*)d_in[7];
    const float* b2   = (const float*)d_in[8];
    const float* W3   = (const float*)d_in[9];
    const float* b3   = (const float*)d_in[10];
    const float* W4   = (const float*)d_in[11];
    const float* b4   = (const float*)d_in[12];
    const float* Wq   = (const float*)d_in[13];
    const float* bq   = (const float*)d_in[14];
    const float* Wk   = (const float*)d_in[15];
    const float* bk   = (const float*)d_in[16];
    const float* gq   = (const float*)d_in[17];
    const float* betaq= (const float*)d_in[18];
    const float* gk   = (const float*)d_in[19];
    const float* betak= (const float*)d_in[20];
    float* out = (float*)d_out;

    float *p_h1, *p_h2, *p_enc, *p_ln, *p_qk;
    cudaGetSymbolAddress((void**)&p_h1, g_h1);
    cudaGetSymbolAddress((void**)&p_h2, g_h2);
    cudaGetSymbolAddress((void**)&p_enc, g_enc);
    cudaGetSymbolAddress((void**)&p_ln, g_ln);
    cudaGetSymbolAddress((void**)&p_qk, g_qk);

    // MLP layer 1 (two halves: true rows [0,8192), sim rows [8192,16384))
    sgemm_bias<<<dim3(4, 64), 256>>>(Xt, INF_DIM, W1, HID, b1, p_h1, HID, HID, INF_DIM, 1);
    sgemm_bias<<<dim3(4, 64), 256>>>(Xs, INF_DIM, W1, HID, b1, p_h1 + (size_t)NTOK * HID, HID, HID, INF_DIM, 1);
    // layers 2,3
    sgemm_bias<<<dim3(4, 128), 256>>>(p_h1, HID, W2, HID, b2, p_h2, HID, HID, HID, 1);
    sgemm_bias<<<dim3(4, 128), 256>>>(p_h2, HID, W3, HID, b3, p_h1, HID, HID, HID, 1);
    // layer 4 (no relu) -> enc
    sgemm_bias<<<dim3(1, 128), 256>>>(p_h1, HID, W4, DD, b4, p_enc, DD, DD, HID, 0);
    // layernorm
    ln_kernel<<<NTOK2 / 8, 256>>>(gq, betaq, gk, betak);
    // projections: q (rows 0..8191), k (rows 8192..16383)
    sgemm_bias<<<dim3(4, 64), 256>>>(p_ln, DD, Wq, HH * DD, bq, p_qk, HH * DD, HH * DD, DD, 0);
    sgemm_bias<<<dim3(4, 64), 256>>>(p_ln + (size_t)NTOK * DD, DD, Wk, HH * DD, bk,
                                     p_qk + (size_t)NTOK * (HH * DD), HH * DD, HH * DD, DD, 0);
    // scores (16 independent 2048x2048x128 NT gemms)
    sgemm_nt_scores<<<dim3(16, 16, 16), 256>>>(p_qk, p_qk + (size_t)NTOK * (HH * DD));
    // top-k + quantiles + quantile outputs
    topk_quantile_kernel<<<NROW / 4, 128>>>(err, y, ypr, out);
    // passthrough copies
    copy_kernel<<<288, 256>>>(y, ypr, err, out);
    // scalar score
    reduce_kernel<<<1, 1024>>>(out);
}